// round 6
// baseline (speedup 1.0000x reference)
#include <cuda_runtime.h>
#include <cuda_bf16.h>
#include <cstdint>

// Integration_4123168604342
// x: (T=128, B=4, E=10000, F=16) f32, dummy_index: int scalar
// out: (128, 4, 10000, 15) f32 = tanh(cumsum_T(f * dt))
//
// R6: LDG.64 mapping — 8 lanes per (b,e) group, lane owns 2 channels (float2).
// Halves chip-wide load-instruction count (same bytes) to test/relieve the
// per-SM memory-request-rate limit that R4/R5 plateaued on (both exactly
// 106.016us kernel @ DRAM 70%). Depth-8 rotating float2 pipeline (2KB/warp
// in flight, same as R5). __ldcs on loads (no reuse).

#define T_DIM   128
#define B_DIM   4
#define E_DIM   10000
#define F_DIM   16
#define FO_DIM  15
#define DEPTH   8
#define BE_DIM  (B_DIM * E_DIM)                // 40000 groups
#define STRIDE_T2  ((size_t)BE_DIM * 8)        // 320000 float2 per t (input)
#define STRIDE_TO  ((size_t)BE_DIM * FO_DIM)   // 600000 floats per t (output)

__device__ __forceinline__ float tanh_fast(float x) {
    float y;
    asm("tanh.approx.f32 %0, %1;" : "=f"(y) : "f"(x));
    return y;
}

__global__ __launch_bounds__(256)
void integration_kernel(const float* __restrict__ x,
                        const int* __restrict__ didx,
                        float* __restrict__ out) {
    const int gid   = blockIdx.x * blockDim.x + threadIdx.x;   // 0..319999
    const int group = gid >> 3;        // (b,e) flat index
    const int sub   = gid & 7;         // which float2 chunk (channels 2*sub, 2*sub+1)
    if (group >= BE_DIM) return;

    const int d = *didx;               // dummy (time) channel, uniform
    const int d_sub  = d >> 1;         // lane (within 8) holding the t channel
    const bool d_hi  = (d & 1) != 0;   // which component of that float2

    const int ch0 = 2 * sub;
    const int ch1 = 2 * sub + 1;
    const bool skip0 = (ch0 == d);
    const bool skip1 = (ch1 == d);
    const int off0 = ch0 - (ch0 > d ? 1 : 0);
    const int off1 = ch1 - (ch1 > d ? 1 : 0);

    const float2* __restrict__ xp = (const float2*)x + (size_t)group * 8 + sub;
    float* __restrict__ opb = out + (size_t)group * FO_DIM;

    // ---- prologue: rows 0..7 in flight (8 x LDG.64) ----
    float2 b0 = __ldcs(xp);
    float2 b1 = __ldcs(xp + STRIDE_T2);
    float2 b2 = __ldcs(xp + 2 * STRIDE_T2);
    float2 b3 = __ldcs(xp + 3 * STRIDE_T2);
    float2 b4 = __ldcs(xp + 4 * STRIDE_T2);
    float2 b5 = __ldcs(xp + 5 * STRIDE_T2);
    float2 b6 = __ldcs(xp + 6 * STRIDE_T2);
    float2 b7 = __ldcs(xp + 7 * STRIDE_T2);

    const float t0 = __shfl_sync(0xFFFFFFFFu, d_hi ? b0.y : b0.x, d_sub, 8);
    const float t1 = __shfl_sync(0xFFFFFFFFu, d_hi ? b1.y : b1.x, d_sub, 8);

    // t = 0: dt0 = t[0] + t[1]
    const float dt0 = t0 + t1;
    float acc0 = b0.x * dt0;
    float acc1 = b0.y * dt0;
    if (!skip0) opb[off0] = tanh_fast(acc0);
    if (!skip1) opb[off1] = tanh_fast(acc1);
    float prev_t = t0;

    // consume buffer bv as row (base+k), then reload bv from row (base+k+DEPTH)
#define STEP(bv, k) do {                                                     \
        const float tl = d_hi ? (bv).y : (bv).x;                             \
        const float tc = __shfl_sync(0xFFFFFFFFu, tl, d_sub, 8);             \
        const float dt = tc - prev_t;                                        \
        acc0 = fmaf((bv).x, dt, acc0);                                       \
        acc1 = fmaf((bv).y, dt, acc1);                                       \
        float* o = opb + (size_t)(base + (k)) * STRIDE_TO;                   \
        if (!skip0) o[off0] = tanh_fast(acc0);                               \
        if (!skip1) o[off1] = tanh_fast(acc1);                               \
        prev_t = tc;                                                         \
        (bv) = __ldcs(xp + (size_t)(base + (k) + DEPTH) * STRIDE_T2);        \
    } while (0)

#define STEP_NOLOAD(bv, k) do {                                              \
        const float tl = d_hi ? (bv).y : (bv).x;                             \
        const float tc = __shfl_sync(0xFFFFFFFFu, tl, d_sub, 8);             \
        const float dt = tc - prev_t;                                        \
        acc0 = fmaf((bv).x, dt, acc0);                                       \
        acc1 = fmaf((bv).y, dt, acc1);                                       \
        float* o = opb + (size_t)(base + (k)) * STRIDE_TO;                   \
        if (!skip0) o[off0] = tanh_fast(acc0);                               \
        if (!skip1) o[off1] = tanh_fast(acc1);                               \
        prev_t = tc;                                                         \
    } while (0)

    // ---- steady state: rows 0..119 consumed, rows 8..127 reloaded ----
    #pragma unroll 1
    for (int base = 0; base < T_DIM - DEPTH; base += DEPTH) {
        if (base > 0) STEP(b0, 0);
        else          b0 = __ldcs(xp + (size_t)DEPTH * STRIDE_T2);  // row 0 done
        STEP(b1, 1);
        STEP(b2, 2);
        STEP(b3, 3);
        STEP(b4, 4);
        STEP(b5, 5);
        STEP(b6, 6);
        STEP(b7, 7);
    }

    // ---- epilogue: rows 120..127 ----
    {
        const int base = T_DIM - DEPTH;
        STEP_NOLOAD(b0, 0);
        STEP_NOLOAD(b1, 1);
        STEP_NOLOAD(b2, 2);
        STEP_NOLOAD(b3, 3);
        STEP_NOLOAD(b4, 4);
        STEP_NOLOAD(b5, 5);
        STEP_NOLOAD(b6, 6);
        STEP_NOLOAD(b7, 7);
    }

#undef STEP
#undef STEP_NOLOAD
}

extern "C" void kernel_launch(void* const* d_in, const int* in_sizes, int n_in,
                              void* d_out, int out_size) {
    const float* x   = (const float*)d_in[0];
    const int* didx  = (const int*)d_in[1];
    float* out       = (float*)d_out;

    const int total_threads = BE_DIM * 8;          // 320000
    const int block = 256;
    const int grid = (total_threads + block - 1) / block;   // 1250
    integration_kernel<<<grid, block>>>(x, didx, out);
}